// round 14
// baseline (speedup 1.0000x reference)
#include <cuda_runtime.h>
#include <cuda_bf16.h>
#include <cstdint>

#define EMB    512
#define HID    512
#define NCLASS 50257
#define BATCH  64
#define STEPS  256
#define FOURH  2048

// ---------------- scratch (device globals; no mallocs allowed) ---------------
__device__ float          g_xw[STEPS * BATCH * FOURH]; // 128 MiB input proj
__device__ __align__(16) __nv_bfloat16 g_h[2 * BATCH * HID]; // dbl-buffered h
__device__ float          g_hf[BATCH * HID];           // fp32 h at final step
__device__ float          g_bsum[FOURH];               // bi + bh
// 4 independent barrier domains; each counter/phase on its own 128B line
__device__ __align__(128) unsigned g_barc[4 * 32];
__device__ __align__(128) unsigned g_barp[4 * 32];

// ---------------- helpers ------------------------------------------------------
__device__ __forceinline__ float fsigmoid_(float x) {
    return __fdividef(1.0f, 1.0f + __expf(-x));
}
__device__ __forceinline__ float ftanh_(float x) {
    return 2.0f * __fdividef(1.0f, 1.0f + __expf(-2.0f * x)) - 1.0f;
}
// tf32 helpers
__device__ __forceinline__ unsigned cvt_tf32(float v) {
    unsigned r;
    asm("cvt.rna.tf32.f32 %0, %1;" : "=r"(r) : "f"(v));
    return r;
}
__device__ __forceinline__ uint4 cvt_tf32x4(float4 v) {
    uint4 r;
    r.x = cvt_tf32(v.x); r.y = cvt_tf32(v.y);
    r.z = cvt_tf32(v.z); r.w = cvt_tf32(v.w);
    return r;
}
__device__ __forceinline__ void mma_tf32(float* c, const unsigned* a, const unsigned* b) {
    asm("mma.sync.aligned.m16n8k8.row.col.f32.tf32.tf32.f32 "
        "{%0,%1,%2,%3}, {%4,%5,%6,%7}, {%8,%9}, {%0,%1,%2,%3};"
        : "+f"(c[0]), "+f"(c[1]), "+f"(c[2]), "+f"(c[3])
        : "r"(a[0]), "r"(a[1]), "r"(a[2]), "r"(a[3]), "r"(b[0]), "r"(b[1]));
}
// bf16 helpers (lstm kernel)
__device__ __forceinline__ unsigned pack_bf16(float lo, float hi) {
    unsigned r;
    asm("cvt.rn.bf16x2.f32 %0, %1, %2;" : "=r"(r) : "f"(hi), "f"(lo));
    return r;
}
__device__ __forceinline__ void mma_bf16(float* c, const unsigned* a, const unsigned* b) {
    asm("mma.sync.aligned.m16n8k16.row.col.f32.bf16.bf16.f32 "
        "{%0,%1,%2,%3}, {%4,%5,%6,%7}, {%8,%9}, {%0,%1,%2,%3};"
        : "+f"(c[0]), "+f"(c[1]), "+f"(c[2]), "+f"(c[3])
        : "r"(a[0]), "r"(a[1]), "r"(a[2]), "r"(a[3]), "r"(b[0]), "r"(b[1]));
}
// mbarrier helpers
#define MBAR_INIT(a, c) \
    asm volatile("mbarrier.init.shared.b64 [%0], %1;" :: "r"(a), "r"(c) : "memory")
#define MBAR_EXPECT_TX(a, b) \
    asm volatile("mbarrier.arrive.expect_tx.shared.b64 _, [%0], %1;" :: "r"(a), "r"(b) : "memory")
__device__ __forceinline__ void mbar_wait_parity(unsigned a, unsigned par) {
    asm volatile(
        "{\n\t.reg .pred P1;\n\t"
        "WL_%=:\n\t"
        "mbarrier.try_wait.parity.acquire.cta.shared::cta.b64 P1, [%0], %1, 0x989680;\n\t"
        "@P1 bra.uni WD_%=;\n\t"
        "bra.uni WL_%=;\n\t"
        "WD_%=:\n\t}"
        :: "r"(a), "r"(par) : "memory");
}

// ---------------- per-domain grid barrier (32 CTAs each) -----------------------
__device__ __forceinline__ void domain_barrier(int dom, unsigned target) {
    __syncthreads();
    if (threadIdx.x == 0) {
        unsigned* cp = &g_barc[dom * 32];
        unsigned* pp = &g_barp[dom * 32];
        unsigned old;
        asm volatile("atom.release.gpu.global.add.u32 %0, [%1], 1;"
                     : "=r"(old) : "l"(cp) : "memory");
        if (old + 1u == target * 32u) {
            asm volatile("st.release.gpu.global.u32 [%0], %1;"
                         :: "l"(pp), "r"(target) : "memory");
        } else {
            unsigned cur;
            do {
                asm volatile("ld.acquire.gpu.global.u32 %0, [%1];"
                             : "=r"(cur) : "l"(pp) : "memory");
            } while (cur < target);
        }
    }
    __syncthreads();
}

// ---------------- kernel 0: prep ------------------------------------------------
__global__ void prep_kernel(const float* __restrict__ bi, const float* __restrict__ bh) {
    int i = blockIdx.x * blockDim.x + threadIdx.x;
    int stride = gridDim.x * blockDim.x;
    if (i < 128) { g_barc[i] = 0u; g_barp[i] = 0u; }
    if (i < FOURH) g_bsum[i] = bi[i] + bh[i];
    unsigned* gh = (unsigned*)g_h;                 // 2*64*512 bf16 = 32768 u32
    for (int j = i; j < 32768; j += stride) gh[j] = 0u;
}

// ---------------- kernel 1: xw = gather(emb, X) @ Wi + bsum  (tf32 HMMA) -------
#define XW_AS(buf, r, k) sm_u[(buf) * 4608 + (r) * 36 + (k)]
#define XW_BS(buf, k, c) sm_u[9216 + (buf) * 4224 + (k) * 132 + (c)]
#define SMEM_XW ((9216 + 8448) * 4)

__global__ __launch_bounds__(256, 2) void xw_tf32_kernel(
    const int* __restrict__ X, const float* __restrict__ emb,
    const float* __restrict__ Wi) {
    extern __shared__ __align__(16) unsigned sm_u[];
    __shared__ int tok[128];

    const int tid = threadIdx.x;
    const int m0 = blockIdx.y * 128;
    const int n0 = blockIdx.x * 128;
    const int lane = tid & 31, wrp = tid >> 5;
    const int wm = wrp >> 2, wn = wrp & 3;
    const int g = lane >> 2, tig = lane & 3;

    const int arow_b = tid >> 3, akq = tid & 7;
    const int bk_b   = tid >> 5, bc4 = tid & 31;

    if (tid < 128) {
        int m = m0 + tid;
        tok[tid] = X[(m & 63) * STEPS + (m >> 6)];
    }
    __syncthreads();

    float acc[4][4][4];
#pragma unroll
    for (int mt = 0; mt < 4; ++mt)
#pragma unroll
        for (int nt = 0; nt < 4; ++nt)
#pragma unroll
            for (int j = 0; j < 4; ++j) acc[mt][nt][j] = 0.0f;

    float4 pa[4], pb[4];
#pragma unroll
    for (int q = 0; q < 4; ++q) {
        pa[q] = *(const float4*)(emb + (size_t)tok[arow_b + q * 32] * EMB + akq * 4);
        pb[q] = *(const float4*)(Wi + (size_t)(bk_b + q * 8) * FOURH + n0 + bc4 * 4);
    }

    int cur = 0;
    for (int kt = 0; kt < EMB; kt += 32) {
#pragma unroll
        for (int q = 0; q < 4; ++q) {
            *(uint4*)&XW_AS(cur, arow_b + q * 32, akq * 4) = cvt_tf32x4(pa[q]);
            *(uint4*)&XW_BS(cur, bk_b + q * 8, bc4 * 4)    = cvt_tf32x4(pb[q]);
        }
        if (kt + 32 < EMB) {
            int kn = kt + 32;
#pragma unroll
            for (int q = 0; q < 4; ++q) {
                pa[q] = *(const float4*)(emb + (size_t)tok[arow_b + q * 32] * EMB + kn + akq * 4);
                pb[q] = *(const float4*)(Wi + (size_t)(kn + bk_b + q * 8) * FOURH + n0 + bc4 * 4);
            }
        }
        __syncthreads();

#pragma unroll
        for (int k8 = 0; k8 < 4; ++k8) {
            const int k0 = k8 * 8;
            unsigned a[4][4], b[4][2];
#pragma unroll
            for (int mt = 0; mt < 4; ++mt) {
                int r = wm * 64 + mt * 16 + g;
                a[mt][0] = XW_AS(cur, r,     k0 + tig);
                a[mt][1] = XW_AS(cur, r + 8, k0 + tig);
                a[mt][2] = XW_AS(cur, r,     k0 + tig + 4);
                a[mt][3] = XW_AS(cur, r + 8, k0 + tig + 4);
            }
#pragma unroll
            for (int nt = 0; nt < 4; ++nt) {
                int c = wn * 32 + nt * 8 + g;
                b[nt][0] = XW_BS(cur, k0 + tig,     c);
                b[nt][1] = XW_BS(cur, k0 + tig + 4, c);
            }
#pragma unroll
            for (int mt = 0; mt < 4; ++mt)
#pragma unroll
                for (int nt = 0; nt < 4; ++nt)
                    mma_tf32(acc[mt][nt], a[mt], b[nt]);
        }
        cur ^= 1;
    }

    float bs0[4], bs1[4];
#pragma unroll
    for (int nt = 0; nt < 4; ++nt) {
        int c = n0 + wn * 32 + nt * 8 + tig * 2;
        bs0[nt] = g_bsum[c];
        bs1[nt] = g_bsum[c + 1];
    }
#pragma unroll
    for (int mt = 0; mt < 4; ++mt) {
        int r = m0 + wm * 64 + mt * 16 + g;
#pragma unroll
        for (int nt = 0; nt < 4; ++nt) {
            int c = n0 + wn * 32 + nt * 8 + tig * 2;
            *(float2*)(g_xw + (size_t)r * FOURH + c) =
                make_float2(acc[mt][nt][0] + bs0[nt], acc[mt][nt][1] + bs1[nt]);
            *(float2*)(g_xw + (size_t)(r + 8) * FOURH + c) =
                make_float2(acc[mt][nt][2] + bs0[nt], acc[mt][nt][3] + bs1[nt]);
        }
    }
}

// ---------------- kernel 2: persistent LSTM, bf16 mma, bulk-copy staging ------
// 128 CTAs = 32 col-groups (16 hidden units = 64 gate cols) x 4 batch-groups(16).
// CTA tile: 16 batches x 64 gate cols, K=512. Warps: ntp(4, 16-col) x kh(2).
// h staged per step via 16 x 1KB cp.async.bulk into padded rows (mbarrier).
// smem (u32): h_s[16][260] | wf[32 i16][8 nt][32 ln][2] | spre2 f32[2][64][17] | mbar
#define LSTM_SMEM ((4160 + 16384 + 2176 + 4) * 4)

__global__ __launch_bounds__(256, 1) void lstm_bf16_kernel(const float* __restrict__ Wh) {
    extern __shared__ __align__(16) unsigned smu[];
    unsigned* h_s   = smu;                          // [16][260] u32 (bf16x2)
    unsigned* wf    = smu + 4160;                   // [32][8][32][2]
    float*    spre2 = (float*)(smu + 4160 + 16384); // [2][64][17]
    // u64 mbarrier at u32 offset 22720 (byte 90880, 16B aligned)

    const int tid  = threadIdx.x;
    const int cta  = blockIdx.x;
    const int colg = cta >> 2;          // 0..31 (16 hidden units each)
    const int bg   = cta & 3;           // batch quarter (barrier domain)
    const int lane = tid & 31, wid = tid >> 5;
    const int g = lane >> 2, tig = lane & 3;
    const int ntp = wid & 3, kh = wid >> 2;

    const unsigned smem_base = (unsigned)__cvta_generic_to_shared(smu);
    const unsigned hs_addr = smem_base;
    const unsigned mb_addr = smem_base + 22720u * 4u;

    // one-time: pack this CTA's 64 Wh columns into bf16 B-fragment layout
    for (int idx = tid; idx < 16384; idx += 256) {
        int reg = idx & 1;
        int ln  = (idx >> 1) & 31;
        int nt8 = (idx >> 6) & 7;               // n-tile 0..7
        int i16 = idx >> 9;                     // k16 tile 0..31
        int lg = ln >> 2, ltig = ln & 3;
        int k0 = i16 * 16 + 2 * ltig + reg * 8;
        int c  = nt8 * 8 + lg;                  // local col 0..63
        int gc = (c >> 4) * HID + colg * 16 + (c & 15);
        wf[idx] = pack_bf16(Wh[(size_t)k0 * FOURH + gc],
                            Wh[(size_t)(k0 + 1) * FOURH + gc]);
    }
    if (tid == 0) MBAR_INIT(mb_addr, 1);

    const int ub = tid >> 4, uu = tid & 15;     // update: local batch, unit
    float creg = 0.0f;

    const unsigned* ha = h_s + g * 260 + tig;
    const unsigned* hb = ha + 8 * 260;

    __syncthreads();

    for (int t = 0; t < STEPS; ++t) {
        const __nv_bfloat16* hin = g_h + (t & 1) * BATCH * HID;
        __nv_bfloat16*      hout = g_h + ((t + 1) & 1) * BATCH * HID;
        const float* xwt = g_xw + (size_t)t * BATCH * FOURH
                           + (size_t)(bg * 16 + ub) * FOURH + colg * 16 + uu;

        // prefetch this step's xw gate biases
        float x0 = __ldcs(xwt);
        float x1 = __ldcs(xwt + 512);
        float x2 = __ldcs(xwt + 1024);
        float x3 = __ldcs(xwt + 1536);

        // stage 16 bf16 h rows (16 KB) via bulk copies into padded rows
        if (tid == 0) {
            asm volatile("fence.proxy.async;" ::: "memory");
            MBAR_EXPECT_TX(mb_addr, 16384u);
#pragma unroll
            for (int r = 0; r < 16; ++r) {
                asm volatile(
                    "cp.async.bulk.shared::cta.global.mbarrier::complete_tx::bytes "
                    "[%0], [%1], %2, [%3];"
                    :: "r"(hs_addr + (unsigned)(r * 1040)),
                       "l"((const char*)hin + (size_t)(bg * 16 + r) * 1024),
                       "r"(1024u), "r"(mb_addr)
                    : "memory");
            }
        }
        mbar_wait_parity(mb_addr, (unsigned)(t & 1));

        // bf16 mma over this warp's k-half (16 k16-tiles, 2 n-tiles)
        float acc0[4] = {0.f, 0.f, 0.f, 0.f};
        float acc1[4] = {0.f, 0.f, 0.f, 0.f};
#pragma unroll 8
        for (int i16 = kh * 16; i16 < kh * 16 + 16; ++i16) {
            unsigned a[4];
            a[0] = ha[i16 * 8];
            a[1] = hb[i16 * 8];
            a[2] = ha[i16 * 8 + 4];
            a[3] = hb[i16 * 8 + 4];
            const unsigned* wb = wf + ((i16 * 8 + ntp * 2) * 32 + lane) * 2;
            uint2 b0 = *(const uint2*)wb;
            uint2 b1 = *(const uint2*)(wb + 64);
            mma_bf16(acc0, a, (const unsigned*)&b0);
            mma_bf16(acc1, a, (const unsigned*)&b1);
        }

        // write per-k-half partials: spre2[kh][col 0..63][batch 0..15]
        {
            float* sp = spre2 + kh * 1088;
            int c0 = ntp * 16 + tig * 2;
            sp[(c0)     * 17 + g]     = acc0[0];
            sp[(c0 + 1) * 17 + g]     = acc0[1];
            sp[(c0)     * 17 + g + 8] = acc0[2];
            sp[(c0 + 1) * 17 + g + 8] = acc0[3];
            sp[(c0 + 8) * 17 + g]     = acc1[0];
            sp[(c0 + 9) * 17 + g]     = acc1[1];
            sp[(c0 + 8) * 17 + g + 8] = acc1[2];
            sp[(c0 + 9) * 17 + g + 8] = acc1[3];
        }
        __syncthreads();

        // cell update: thread -> (local batch ub 0..15, unit uu 0..15)
        {
            float pi = spre2[(0  + uu) * 17 + ub] + spre2[1088 + (0  + uu) * 17 + ub] + x0;
            float pf = spre2[(16 + uu) * 17 + ub] + spre2[1088 + (16 + uu) * 17 + ub] + x1;
            float pg = spre2[(32 + uu) * 17 + ub] + spre2[1088 + (32 + uu) * 17 + ub] + x2;
            float po = spre2[(48 + uu) * 17 + ub] + spre2[1088 + (48 + uu) * 17 + ub] + x3;
            float ig = fsigmoid_(pi);
            float fg = fsigmoid_(pf);
            float gg = ftanh_(pg);
            float og = fsigmoid_(po);
            creg = fg * creg + ig * gg;
            float hh = og * ftanh_(creg);
            size_t hidx = (size_t)(bg * 16 + ub) * HID + colg * 16 + uu;
            hout[hidx] = __float2bfloat16(hh);
            if (t == STEPS - 1) g_hf[hidx] = hh;   // fp32 copy for outproj
        }
        domain_barrier(bg, (unsigned)(t + 1));
    }
}

// ---------------- kernel 3: out^T tile via tf32 mma ---------------------------
// C tile: M=64 (batch) x N=256 (classes), K=512, BK=16. 8 warps = 8 n-groups(32).
// A = h (fp32->tf32), B = Wout rows; SCALAR stores (NCLASS odd -> rows are only
// 4B aligned for odd batch rows; float2 would fault).
#define OP_AS(buf, k, b) smo[(buf) * 1088 + (k) * 68 + (b)]
#define OP_BS(buf, k, c) smo[2176 + (buf) * 4224 + (k) * 264 + (c)]
#define SMEM_OP ((2176 + 8448) * 4)

__global__ __launch_bounds__(256, 2) void outproj_tf32_kernel(
    const float* __restrict__ Wout, const float* __restrict__ bout,
    float* __restrict__ out) {
    extern __shared__ __align__(16) unsigned smo[];

    const int tid = threadIdx.x;
    const int n0 = blockIdx.x * 256;
    const int lane = tid & 31, wrp = tid >> 5;   // wrp = n-group 0..7
    const int g = lane >> 2, tig = lane & 3;
    const float* h = g_hf;

    const int brow = tid >> 2, bc4 = tid & 3;    // B loader: row 0..63 (+64q)

    float acc[4][4][4];
#pragma unroll
    for (int mt = 0; mt < 4; ++mt)
#pragma unroll
        for (int nt = 0; nt < 4; ++nt)
#pragma unroll
            for (int j = 0; j < 4; ++j) acc[mt][nt][j] = 0.0f;

    // prefetch k-tile 0
    float  ph[4];
    float4 pw[4];
#pragma unroll
    for (int q = 0; q < 4; ++q) {
        int id = tid + q * 256;
        ph[q] = h[(id >> 4) * HID + (id & 15)];
        int row = n0 + brow + q * 64;
        pw[q] = (row < NCLASS) ? *(const float4*)(Wout + (size_t)row * HID + bc4 * 4)
                               : make_float4(0.f, 0.f, 0.f, 0.f);
    }

    int cur = 0;
    for (int kt = 0; kt < HID; kt += 16) {
#pragma unroll
        for (int q = 0; q < 4; ++q) {
            int id = tid + q * 256;
            OP_AS(cur, id & 15, id >> 4) = cvt_tf32(ph[q]);
            uint4 w = cvt_tf32x4(pw[q]);
            OP_BS(cur, bc4 * 4 + 0, brow + q * 64) = w.x;
            OP_BS(cur, bc4 * 4 + 1, brow + q * 64) = w.y;
            OP_BS(cur, bc4 * 4 + 2, brow + q * 64) = w.z;
            OP_BS(cur, bc4 * 4 + 3, brow + q * 64) = w.w;
        }
        if (kt + 16 < HID) {
            int kn = kt + 16;
#pragma unroll
            for (int q = 0; q < 4; ++q) {
                int id = tid + q * 256;
                ph[q] = h[(id >> 4) * HID + kn + (id & 15)];
                int row = n0 + brow + q * 64;
                pw[q] = (row < NCLASS) ? *(const float4*)(Wout + (size_t)row * HID + kn + bc4 * 4)
                                       : make_float4(0.f, 0.f, 0.f, 0.f);
            }
        }
        __syncthreads();

#pragma unroll
        for (int k8 = 0; k8 < 2; ++k8) {
            const int k0 = k8 * 8;
            unsigned a[4][4], b[4][2];
#pragma unroll
            for (int mt = 0; mt < 4; ++mt) {
                int r = mt * 16 + g;
                a[mt][0] = OP_AS(cur, k0 + tig,     r);
                a[mt][1] = OP_AS(cur, k0 + tig,     r + 8);
                a[mt][2] = OP_AS(cur, k0 + tig + 4, r);
                a[mt][3] = OP_AS(cur, k0 + tig + 4, r + 8);
            }
#pragma unroll
            for (int nt = 0; nt < 4; ++nt) {
                int c = wrp * 32 + nt * 8 + g;
                b[nt][0] = OP_BS(cur, k0 + tig,     c);
                b[nt][1] = OP_BS(cur, k0 + tig + 4, c);
            }
#pragma unroll
            for (int mt = 0; mt < 4; ++mt)
#pragma unroll
                for (int nt = 0; nt < 4; ++nt)
                    mma_tf32(acc[mt][nt], a[mt], b[nt]);
        }
        cur ^= 1;
    }

    // epilogue: scalar stores (row stride NCLASS is odd -> no vector alignment)
#pragma unroll
    for (int nt = 0; nt < 4; ++nt) {
        int n = n0 + wrp * 32 + nt * 8 + tig * 2;
        if (n >= NCLASS) continue;
        float bo0 = bout[n];
        bool has1 = (n + 1 < NCLASS);
        float bo1 = has1 ? bout[n + 1] : 0.0f;
#pragma unroll
        for (int mt = 0; mt < 4; ++mt) {
            int b0r = mt * 16 + g;
            out[(size_t)b0r * NCLASS + n] = acc[mt][nt][0] + bo0;
            out[(size_t)(b0r + 8) * NCLASS + n] = acc[mt][nt][2] + bo0;
            if (has1) {
                out[(size_t)b0r * NCLASS + n + 1] = acc[mt][nt][1] + bo1;
                out[(size_t)(b0r + 8) * NCLASS + n + 1] = acc[mt][nt][3] + bo1;
            }
        }
    }
}

// ---------------- launch --------------------------------------------------------
extern "C" void kernel_launch(void* const* d_in, const int* in_sizes, int n_in,
                              void* d_out, int out_size) {
    const int*   X    = (const int*)d_in[0];
    const float* emb  = (const float*)d_in[1];
    const float* Wi   = (const float*)d_in[2];
    const float* Wh   = (const float*)d_in[3];
    const float* bi   = (const float*)d_in[4];
    const float* bh   = (const float*)d_in[5];
    // d_in[6..9]: layer-2 params — provably unused by the reference output
    const float* Wout = (const float*)d_in[10];
    const float* bout = (const float*)d_in[11];
    float* out = (float*)d_out;

    // allow >48KB dynamic smem (attribute only, not an allocation; idempotent)
    cudaFuncSetAttribute(lstm_bf16_kernel,
                         cudaFuncAttributeMaxDynamicSharedMemorySize, LSTM_SMEM);
    cudaFuncSetAttribute(xw_tf32_kernel,
                         cudaFuncAttributeMaxDynamicSharedMemorySize, SMEM_XW);
    cudaFuncSetAttribute(outproj_tf32_kernel,
                         cudaFuncAttributeMaxDynamicSharedMemorySize, SMEM_OP);

    prep_kernel<<<64, 256>>>(bi, bh);
    xw_tf32_kernel<<<dim3(FOURH / 128, (STEPS * BATCH) / 128), 256, SMEM_XW>>>(X, emb, Wi);
    lstm_bf16_kernel<<<128, 256, LSTM_SMEM>>>(Wh);
    outproj_tf32_kernel<<<(NCLASS + 255) / 256, 256, SMEM_OP>>>(Wout, bout, out);
}

// round 15
// speedup vs baseline: 1.1919x; 1.1919x over previous
#include <cuda_runtime.h>
#include <cuda_bf16.h>
#include <cstdint>

#define EMB    512
#define HID    512
#define NCLASS 50257
#define BATCH  64
#define STEPS  256
#define FOURH  2048

// ---------------- scratch (device globals; no mallocs allowed) ---------------
__device__ float          g_xw[STEPS * BATCH * FOURH]; // 128 MiB input proj
__device__ __align__(16) __nv_bfloat16 g_h[2 * BATCH * HID]; // dbl-buffered h
__device__ float          g_hf[BATCH * HID];           // fp32 h at final step
__device__ float          g_bsum[FOURH];               // bi + bh
// 4 independent barrier domains; each counter/phase on its own 128B line
__device__ __align__(128) unsigned g_barc[4 * 32];
__device__ __align__(128) unsigned g_barp[4 * 32];

// ---------------- helpers ------------------------------------------------------
__device__ __forceinline__ float fsigmoid_(float x) {
    return __fdividef(1.0f, 1.0f + __expf(-x));
}
__device__ __forceinline__ float ftanh_(float x) {
    return 2.0f * __fdividef(1.0f, 1.0f + __expf(-2.0f * x)) - 1.0f;
}
__device__ __forceinline__ void cpasync16(unsigned dst, const void* src) {
    asm volatile("cp.async.cg.shared.global [%0], [%1], 16;"
                 :: "r"(dst), "l"(src) : "memory");
}
// tf32 helpers
__device__ __forceinline__ unsigned cvt_tf32(float v) {
    unsigned r;
    asm("cvt.rna.tf32.f32 %0, %1;" : "=r"(r) : "f"(v));
    return r;
}
__device__ __forceinline__ uint4 cvt_tf32x4(float4 v) {
    uint4 r;
    r.x = cvt_tf32(v.x); r.y = cvt_tf32(v.y);
    r.z = cvt_tf32(v.z); r.w = cvt_tf32(v.w);
    return r;
}
__device__ __forceinline__ void mma_tf32(float* c, const unsigned* a, const unsigned* b) {
    asm("mma.sync.aligned.m16n8k8.row.col.f32.tf32.tf32.f32 "
        "{%0,%1,%2,%3}, {%4,%5,%6,%7}, {%8,%9}, {%0,%1,%2,%3};"
        : "+f"(c[0]), "+f"(c[1]), "+f"(c[2]), "+f"(c[3])
        : "r"(a[0]), "r"(a[1]), "r"(a[2]), "r"(a[3]), "r"(b[0]), "r"(b[1]));
}
// bf16 helpers (lstm kernel)
__device__ __forceinline__ unsigned pack_bf16(float lo, float hi) {
    unsigned r;
    asm("cvt.rn.bf16x2.f32 %0, %1, %2;" : "=r"(r) : "f"(hi), "f"(lo));
    return r;
}
__device__ __forceinline__ void mma_bf16(float* c, const unsigned* a, const unsigned* b) {
    asm("mma.sync.aligned.m16n8k16.row.col.f32.bf16.bf16.f32 "
        "{%0,%1,%2,%3}, {%4,%5,%6,%7}, {%8,%9}, {%0,%1,%2,%3};"
        : "+f"(c[0]), "+f"(c[1]), "+f"(c[2]), "+f"(c[3])
        : "r"(a[0]), "r"(a[1]), "r"(a[2]), "r"(a[3]), "r"(b[0]), "r"(b[1]));
}

// ---------------- per-domain grid barrier (32 CTAs each) -----------------------
__device__ __forceinline__ void domain_barrier(int dom, unsigned target) {
    __syncthreads();
    if (threadIdx.x == 0) {
        unsigned* cp = &g_barc[dom * 32];
        unsigned* pp = &g_barp[dom * 32];
        unsigned old;
        asm volatile("atom.release.gpu.global.add.u32 %0, [%1], 1;"
                     : "=r"(old) : "l"(cp) : "memory");
        if (old + 1u == target * 32u) {
            asm volatile("st.release.gpu.global.u32 [%0], %1;"
                         :: "l"(pp), "r"(target) : "memory");
        } else {
            unsigned cur;
            do {
                asm volatile("ld.acquire.gpu.global.u32 %0, [%1];"
                             : "=r"(cur) : "l"(pp) : "memory");
            } while (cur < target);
        }
    }
    __syncthreads();
}

// ---------------- kernel 0: prep ------------------------------------------------
__global__ void prep_kernel(const float* __restrict__ bi, const float* __restrict__ bh) {
    int i = blockIdx.x * blockDim.x + threadIdx.x;
    int stride = gridDim.x * blockDim.x;
    if (i < 128) { g_barc[i] = 0u; g_barp[i] = 0u; }
    if (i < FOURH) g_bsum[i] = bi[i] + bh[i];
    unsigned* gh = (unsigned*)g_h;                 // 2*64*512 bf16 = 32768 u32
    for (int j = i; j < 32768; j += stride) gh[j] = 0u;
}

// ---------------- kernel 1: xw = gather(emb, X) @ Wi + bsum  (tf32 HMMA) -------
#define XW_AS(buf, r, k) sm_u[(buf) * 4608 + (r) * 36 + (k)]
#define XW_BS(buf, k, c) sm_u[9216 + (buf) * 4224 + (k) * 132 + (c)]
#define SMEM_XW ((9216 + 8448) * 4)

__global__ __launch_bounds__(256, 2) void xw_tf32_kernel(
    const int* __restrict__ X, const float* __restrict__ emb,
    const float* __restrict__ Wi) {
    extern __shared__ __align__(16) unsigned sm_u[];
    __shared__ int tok[128];

    const int tid = threadIdx.x;
    const int m0 = blockIdx.y * 128;
    const int n0 = blockIdx.x * 128;
    const int lane = tid & 31, wrp = tid >> 5;
    const int wm = wrp >> 2, wn = wrp & 3;
    const int g = lane >> 2, tig = lane & 3;

    const int arow_b = tid >> 3, akq = tid & 7;
    const int bk_b   = tid >> 5, bc4 = tid & 31;

    if (tid < 128) {
        int m = m0 + tid;
        tok[tid] = X[(m & 63) * STEPS + (m >> 6)];
    }
    __syncthreads();

    float acc[4][4][4];
#pragma unroll
    for (int mt = 0; mt < 4; ++mt)
#pragma unroll
        for (int nt = 0; nt < 4; ++nt)
#pragma unroll
            for (int j = 0; j < 4; ++j) acc[mt][nt][j] = 0.0f;

    float4 pa[4], pb[4];
#pragma unroll
    for (int q = 0; q < 4; ++q) {
        pa[q] = *(const float4*)(emb + (size_t)tok[arow_b + q * 32] * EMB + akq * 4);
        pb[q] = *(const float4*)(Wi + (size_t)(bk_b + q * 8) * FOURH + n0 + bc4 * 4);
    }

    int cur = 0;
    for (int kt = 0; kt < EMB; kt += 32) {
#pragma unroll
        for (int q = 0; q < 4; ++q) {
            *(uint4*)&XW_AS(cur, arow_b + q * 32, akq * 4) = cvt_tf32x4(pa[q]);
            *(uint4*)&XW_BS(cur, bk_b + q * 8, bc4 * 4)    = cvt_tf32x4(pb[q]);
        }
        if (kt + 32 < EMB) {
            int kn = kt + 32;
#pragma unroll
            for (int q = 0; q < 4; ++q) {
                pa[q] = *(const float4*)(emb + (size_t)tok[arow_b + q * 32] * EMB + kn + akq * 4);
                pb[q] = *(const float4*)(Wi + (size_t)(kn + bk_b + q * 8) * FOURH + n0 + bc4 * 4);
            }
        }
        __syncthreads();

#pragma unroll
        for (int k8 = 0; k8 < 4; ++k8) {
            const int k0 = k8 * 8;
            unsigned a[4][4], b[4][2];
#pragma unroll
            for (int mt = 0; mt < 4; ++mt) {
                int r = wm * 64 + mt * 16 + g;
                a[mt][0] = XW_AS(cur, r,     k0 + tig);
                a[mt][1] = XW_AS(cur, r + 8, k0 + tig);
                a[mt][2] = XW_AS(cur, r,     k0 + tig + 4);
                a[mt][3] = XW_AS(cur, r + 8, k0 + tig + 4);
            }
#pragma unroll
            for (int nt = 0; nt < 4; ++nt) {
                int c = wn * 32 + nt * 8 + g;
                b[nt][0] = XW_BS(cur, k0 + tig,     c);
                b[nt][1] = XW_BS(cur, k0 + tig + 4, c);
            }
#pragma unroll
            for (int mt = 0; mt < 4; ++mt)
#pragma unroll
                for (int nt = 0; nt < 4; ++nt)
                    mma_tf32(acc[mt][nt], a[mt], b[nt]);
        }
        cur ^= 1;
    }

    float bs0[4], bs1[4];
#pragma unroll
    for (int nt = 0; nt < 4; ++nt) {
        int c = n0 + wn * 32 + nt * 8 + tig * 2;
        bs0[nt] = g_bsum[c];
        bs1[nt] = g_bsum[c + 1];
    }
#pragma unroll
    for (int mt = 0; mt < 4; ++mt) {
        int r = m0 + wm * 64 + mt * 16 + g;
#pragma unroll
        for (int nt = 0; nt < 4; ++nt) {
            int c = n0 + wn * 32 + nt * 8 + tig * 2;
            *(float2*)(g_xw + (size_t)r * FOURH + c) =
                make_float2(acc[mt][nt][0] + bs0[nt], acc[mt][nt][1] + bs1[nt]);
            *(float2*)(g_xw + (size_t)(r + 8) * FOURH + c) =
                make_float2(acc[mt][nt][2] + bs0[nt], acc[mt][nt][3] + bs1[nt]);
        }
    }
}

// ---------------- kernel 2: persistent LSTM (R12 body, known-good) ------------
// 128 CTAs = 32 col-groups (16 hidden units = 64 gate cols) x 4 batch-groups(16).
// CTA tile: 16 batches x 64 gate cols, K=512. Warps: ntp(4, 16-col) x kh(2).
// h staged per step via per-thread cp.async.cg into padded rows.
// smem (u32): h_s[16][260] | wf[32 i16][8 nt][32 ln][2] | spre2 f32[2][64][17]
#define LSTM_SMEM ((4160 + 16384 + 2176) * 4)

__global__ __launch_bounds__(256, 1) void lstm_bf16_kernel(const float* __restrict__ Wh) {
    extern __shared__ __align__(16) unsigned smu[];
    unsigned* h_s   = smu;                          // [16][260] u32 (bf16x2)
    unsigned* wf    = smu + 4160;                   // [32][8][32][2]
    float*    spre2 = (float*)(smu + 4160 + 16384); // [2][64][17]

    const int tid  = threadIdx.x;
    const int cta  = blockIdx.x;
    const int colg = cta >> 2;          // 0..31 (16 hidden units each)
    const int bg   = cta & 3;           // batch quarter (barrier domain)
    const int lane = tid & 31, wid = tid >> 5;
    const int g = lane >> 2, tig = lane & 3;
    const int ntp = wid & 3, kh = wid >> 2;

    const unsigned hs_addr = (unsigned)__cvta_generic_to_shared(h_s);

    // one-time: pack this CTA's 64 Wh columns into bf16 B-fragment layout
    for (int idx = tid; idx < 16384; idx += 256) {
        int reg = idx & 1;
        int ln  = (idx >> 1) & 31;
        int nt8 = (idx >> 6) & 7;               // n-tile 0..7
        int i16 = idx >> 9;                     // k16 tile 0..31
        int lg = ln >> 2, ltig = ln & 3;
        int k0 = i16 * 16 + 2 * ltig + reg * 8;
        int c  = nt8 * 8 + lg;                  // local col 0..63
        int gc = (c >> 4) * HID + colg * 16 + (c & 15);
        wf[idx] = pack_bf16(Wh[(size_t)k0 * FOURH + gc],
                            Wh[(size_t)(k0 + 1) * FOURH + gc]);
    }

    const int ub = tid >> 4, uu = tid & 15;     // update: local batch, unit
    float creg = 0.0f;

    const unsigned* ha = h_s + g * 260 + tig;
    const unsigned* hb = ha + 8 * 260;

    __syncthreads();

    for (int t = 0; t < STEPS; ++t) {
        const __nv_bfloat16* hin = g_h + (t & 1) * BATCH * HID;
        __nv_bfloat16*      hout = g_h + ((t + 1) & 1) * BATCH * HID;
        const float* xwt = g_xw + (size_t)t * BATCH * FOURH
                           + (size_t)(bg * 16 + ub) * FOURH + colg * 16 + uu;

        // prefetch this step's xw gate biases
        float x0 = __ldcs(xwt);
        float x1 = __ldcs(xwt + 512);
        float x2 = __ldcs(xwt + 1024);
        float x3 = __ldcs(xwt + 1536);

        // stage 16 bf16 h rows (16 KB), row stride 1040 B
#pragma unroll
        for (int j = 0; j < 4; ++j) {
            int i = tid + j * 256;              // 16B chunk 0..1023
            int row = i >> 6, cc = i & 63;
            cpasync16(hs_addr + (unsigned)(row * 1040 + cc * 16),
                      (const char*)hin + (size_t)(bg * 16 + row) * 1024 + cc * 16);
        }
        asm volatile("cp.async.commit_group;");
        asm volatile("cp.async.wait_group 0;" ::: "memory");
        __syncthreads();

        // bf16 mma over this warp's k-half (16 k16-tiles, 2 n-tiles)
        float acc0[4] = {0.f, 0.f, 0.f, 0.f};
        float acc1[4] = {0.f, 0.f, 0.f, 0.f};
#pragma unroll 8
        for (int i16 = kh * 16; i16 < kh * 16 + 16; ++i16) {
            unsigned a[4];
            a[0] = ha[i16 * 8];
            a[1] = hb[i16 * 8];
            a[2] = ha[i16 * 8 + 4];
            a[3] = hb[i16 * 8 + 4];
            const unsigned* wb = wf + ((i16 * 8 + ntp * 2) * 32 + lane) * 2;
            uint2 b0 = *(const uint2*)wb;
            uint2 b1 = *(const uint2*)(wb + 64);
            mma_bf16(acc0, a, (const unsigned*)&b0);
            mma_bf16(acc1, a, (const unsigned*)&b1);
        }

        // write per-k-half partials: spre2[kh][col 0..63][batch 0..15]
        {
            float* sp = spre2 + kh * 1088;
            int c0 = ntp * 16 + tig * 2;
            sp[(c0)     * 17 + g]     = acc0[0];
            sp[(c0 + 1) * 17 + g]     = acc0[1];
            sp[(c0)     * 17 + g + 8] = acc0[2];
            sp[(c0 + 1) * 17 + g + 8] = acc0[3];
            sp[(c0 + 8) * 17 + g]     = acc1[0];
            sp[(c0 + 9) * 17 + g]     = acc1[1];
            sp[(c0 + 8) * 17 + g + 8] = acc1[2];
            sp[(c0 + 9) * 17 + g + 8] = acc1[3];
        }
        __syncthreads();

        // cell update: thread -> (local batch ub 0..15, unit uu 0..15)
        {
            float pi = spre2[(0  + uu) * 17 + ub] + spre2[1088 + (0  + uu) * 17 + ub] + x0;
            float pf = spre2[(16 + uu) * 17 + ub] + spre2[1088 + (16 + uu) * 17 + ub] + x1;
            float pg = spre2[(32 + uu) * 17 + ub] + spre2[1088 + (32 + uu) * 17 + ub] + x2;
            float po = spre2[(48 + uu) * 17 + ub] + spre2[1088 + (48 + uu) * 17 + ub] + x3;
            float ig = fsigmoid_(pi);
            float fg = fsigmoid_(pf);
            float gg = ftanh_(pg);
            float og = fsigmoid_(po);
            creg = fg * creg + ig * gg;
            float hh = og * ftanh_(creg);
            size_t hidx = (size_t)(bg * 16 + ub) * HID + colg * 16 + uu;
            hout[hidx] = __float2bfloat16(hh);
            if (t == STEPS - 1) g_hf[hidx] = hh;   // fp32 copy for outproj
        }
        domain_barrier(bg, (unsigned)(t + 1));
    }
}

// ---------------- kernel 3: out^T tile via tf32 mma (R14, known-good) ---------
// C tile: M=64 (batch) x N=256 (classes), K=512, BK=16. 8 warps = 8 n-groups(32).
// SCALAR stores (NCLASS odd -> odd batch rows are only 4B aligned).
#define OP_AS(buf, k, b) smo[(buf) * 1088 + (k) * 68 + (b)]
#define OP_BS(buf, k, c) smo[2176 + (buf) * 4224 + (k) * 264 + (c)]
#define SMEM_OP ((2176 + 8448) * 4)

__global__ __launch_bounds__(256, 2) void outproj_tf32_kernel(
    const float* __restrict__ Wout, const float* __restrict__ bout,
    float* __restrict__ out) {
    extern __shared__ __align__(16) unsigned smo[];

    const int tid = threadIdx.x;
    const int n0 = blockIdx.x * 256;
    const int lane = tid & 31, wrp = tid >> 5;   // wrp = n-group 0..7
    const int g = lane >> 2, tig = lane & 3;
    const float* h = g_hf;

    const int brow = tid >> 2, bc4 = tid & 3;    // B loader: row 0..63 (+64q)

    float acc[4][4][4];
#pragma unroll
    for (int mt = 0; mt < 4; ++mt)
#pragma unroll
        for (int nt = 0; nt < 4; ++nt)
#pragma unroll
            for (int j = 0; j < 4; ++j) acc[mt][nt][j] = 0.0f;

    // prefetch k-tile 0
    float  ph[4];
    float4 pw[4];
#pragma unroll
    for (int q = 0; q < 4; ++q) {
        int id = tid + q * 256;
        ph[q] = h[(id >> 4) * HID + (id & 15)];
        int row = n0 + brow + q * 64;
        pw[q] = (row < NCLASS) ? *(const float4*)(Wout + (size_t)row * HID + bc4 * 4)
                               : make_float4(0.f, 0.f, 0.f, 0.f);
    }

    int cur = 0;
    for (int kt = 0; kt < HID; kt += 16) {
#pragma unroll
        for (int q = 0; q < 4; ++q) {
            int id = tid + q * 256;
            OP_AS(cur, id & 15, id >> 4) = cvt_tf32(ph[q]);
            uint4 w = cvt_tf32x4(pw[q]);
            OP_BS(cur, bc4 * 4 + 0, brow + q * 64) = w.x;
            OP_BS(cur, bc4 * 4 + 1, brow + q * 64) = w.y;
            OP_BS(cur, bc4 * 4 + 2, brow + q * 64) = w.z;
            OP_BS(cur, bc4 * 4 + 3, brow + q * 64) = w.w;
        }
        if (kt + 16 < HID) {
            int kn = kt + 16;
#pragma unroll
            for (int q = 0; q < 4; ++q) {
                int id = tid + q * 256;
                ph[q] = h[(id >> 4) * HID + kn + (id & 15)];
                int row = n0 + brow + q * 64;
                pw[q] = (row < NCLASS) ? *(const float4*)(Wout + (size_t)row * HID + kn + bc4 * 4)
                                       : make_float4(0.f, 0.f, 0.f, 0.f);
            }
        }
        __syncthreads();

#pragma unroll
        for (int k8 = 0; k8 < 2; ++k8) {
            const int k0 = k8 * 8;
            unsigned a[4][4], b[4][2];
#pragma unroll
            for (int mt = 0; mt < 4; ++mt) {
                int r = mt * 16 + g;
                a[mt][0] = OP_AS(cur, k0 + tig,     r);
                a[mt][1] = OP_AS(cur, k0 + tig,     r + 8);
                a[mt][2] = OP_AS(cur, k0 + tig + 4, r);
                a[mt][3] = OP_AS(cur, k0 + tig + 4, r + 8);
            }
#pragma unroll
            for (int nt = 0; nt < 4; ++nt) {
                int c = wrp * 32 + nt * 8 + g;
                b[nt][0] = OP_BS(cur, k0 + tig,     c);
                b[nt][1] = OP_BS(cur, k0 + tig + 4, c);
            }
#pragma unroll
            for (int mt = 0; mt < 4; ++mt)
#pragma unroll
                for (int nt = 0; nt < 4; ++nt)
                    mma_tf32(acc[mt][nt], a[mt], b[nt]);
        }
        cur ^= 1;
    }

    // epilogue: scalar stores
#pragma unroll
    for (int nt = 0; nt < 4; ++nt) {
        int n = n0 + wrp * 32 + nt * 8 + tig * 2;
        if (n >= NCLASS) continue;
        float bo0 = bout[n];
        bool has1 = (n + 1 < NCLASS);
        float bo1 = has1 ? bout[n + 1] : 0.0f;
#pragma unroll
        for (int mt = 0; mt < 4; ++mt) {
            int b0r = mt * 16 + g;
            out[(size_t)b0r * NCLASS + n] = acc[mt][nt][0] + bo0;
            out[(size_t)(b0r + 8) * NCLASS + n] = acc[mt][nt][2] + bo0;
            if (has1) {
                out[(size_t)b0r * NCLASS + n + 1] = acc[mt][nt][1] + bo1;
                out[(size_t)(b0r + 8) * NCLASS + n + 1] = acc[mt][nt][3] + bo1;
            }
        }
    }
}

// ---------------- launch --------------------------------------------------------
extern "C" void kernel_launch(void* const* d_in, const int* in_sizes, int n_in,
                              void* d_out, int out_size) {
    const int*   X    = (const int*)d_in[0];
    const float* emb  = (const float*)d_in[1];
    const float* Wi   = (const float*)d_in[2];
    const float* Wh   = (const float*)d_in[3];
    const float* bi   = (const float*)d_in[4];
    const float* bh   = (const float*)d_in[5];
    // d_in[6..9]: layer-2 params — provably unused by the reference output
    const float* Wout = (const float*)d_in[10];
    const float* bout = (const float*)d_in[11];
    float* out = (float*)d_out;

    // allow >48KB dynamic smem (attribute only, not an allocation; idempotent)
    cudaFuncSetAttribute(lstm_bf16_kernel,
                         cudaFuncAttributeMaxDynamicSharedMemorySize, LSTM_SMEM);
    cudaFuncSetAttribute(xw_tf32_kernel,
                         cudaFuncAttributeMaxDynamicSharedMemorySize, SMEM_XW);
    cudaFuncSetAttribute(outproj_tf32_kernel,
                         cudaFuncAttributeMaxDynamicSharedMemorySize, SMEM_OP);

    prep_kernel<<<64, 256>>>(bi, bh);
    xw_tf32_kernel<<<dim3(FOURH / 128, (STEPS * BATCH) / 128), 256, SMEM_XW>>>(X, emb, Wi);
    lstm_bf16_kernel<<<128, 256, LSTM_SMEM>>>(Wh);
    outproj_tf32_kernel<<<(NCLASS + 255) / 256, 256, SMEM_OP>>>(Wout, bout, out);
}

// round 16
// speedup vs baseline: 1.2550x; 1.0530x over previous
#include <cuda_runtime.h>
#include <cuda_bf16.h>
#include <cstdint>

#define EMB    512
#define HID    512
#define NCLASS 50257
#define BATCH  64
#define STEPS  256
#define FOURH  2048

// ---------------- scratch (device globals; no mallocs allowed) ---------------
__device__ __align__(16) __nv_bfloat16 g_xw[STEPS * BATCH * FOURH]; // 64 MiB, bf16
__device__ __align__(16) __nv_bfloat16 g_h[2 * BATCH * HID];        // dbl-buffered h
__device__ float          g_hf[BATCH * HID];           // fp32 h at final step
__device__ float          g_bsum[FOURH];               // bi + bh
// 4 independent barrier domains; each counter/phase on its own 128B line
__device__ __align__(128) unsigned g_barc[4 * 32];
__device__ __align__(128) unsigned g_barp[4 * 32];

// ---------------- helpers ------------------------------------------------------
__device__ __forceinline__ float fsigmoid_(float x) {
    return __fdividef(1.0f, 1.0f + __expf(-x));
}
__device__ __forceinline__ float ftanh_(float x) {
    return 2.0f * __fdividef(1.0f, 1.0f + __expf(-2.0f * x)) - 1.0f;
}
__device__ __forceinline__ void cpasync16(unsigned dst, const void* src) {
    asm volatile("cp.async.cg.shared.global [%0], [%1], 16;"
                 :: "r"(dst), "l"(src) : "memory");
}
// tf32 helpers (outproj)
__device__ __forceinline__ unsigned cvt_tf32(float v) {
    unsigned r;
    asm("cvt.rna.tf32.f32 %0, %1;" : "=r"(r) : "f"(v));
    return r;
}
__device__ __forceinline__ uint4 cvt_tf32x4(float4 v) {
    uint4 r;
    r.x = cvt_tf32(v.x); r.y = cvt_tf32(v.y);
    r.z = cvt_tf32(v.z); r.w = cvt_tf32(v.w);
    return r;
}
__device__ __forceinline__ void mma_tf32(float* c, const unsigned* a, const unsigned* b) {
    asm("mma.sync.aligned.m16n8k8.row.col.f32.tf32.tf32.f32 "
        "{%0,%1,%2,%3}, {%4,%5,%6,%7}, {%8,%9}, {%0,%1,%2,%3};"
        : "+f"(c[0]), "+f"(c[1]), "+f"(c[2]), "+f"(c[3])
        : "r"(a[0]), "r"(a[1]), "r"(a[2]), "r"(a[3]), "r"(b[0]), "r"(b[1]));
}
// bf16 helpers: lower 16 bits = first element (lo), upper = second (hi)
__device__ __forceinline__ unsigned pack_bf16(float lo, float hi) {
    unsigned r;
    asm("cvt.rn.bf16x2.f32 %0, %1, %2;" : "=r"(r) : "f"(hi), "f"(lo));
    return r;
}
__device__ __forceinline__ void mma_bf16(float* c, const unsigned* a, const unsigned* b) {
    asm("mma.sync.aligned.m16n8k16.row.col.f32.bf16.bf16.f32 "
        "{%0,%1,%2,%3}, {%4,%5,%6,%7}, {%8,%9}, {%0,%1,%2,%3};"
        : "+f"(c[0]), "+f"(c[1]), "+f"(c[2]), "+f"(c[3])
        : "r"(a[0]), "r"(a[1]), "r"(a[2]), "r"(a[3]), "r"(b[0]), "r"(b[1]));
}
__device__ __forceinline__ float ldcs_bf16(const __nv_bfloat16* p) {
    short s = __ldcs((const short*)p);
    __nv_bfloat16 b = *reinterpret_cast<__nv_bfloat16*>(&s);
    return __bfloat162float(b);
}

// ---------------- per-domain grid barrier (32 CTAs each) -----------------------
__device__ __forceinline__ void domain_barrier(int dom, unsigned target) {
    __syncthreads();
    if (threadIdx.x == 0) {
        unsigned* cp = &g_barc[dom * 32];
        unsigned* pp = &g_barp[dom * 32];
        unsigned old;
        asm volatile("atom.release.gpu.global.add.u32 %0, [%1], 1;"
                     : "=r"(old) : "l"(cp) : "memory");
        if (old + 1u == target * 32u) {
            asm volatile("st.release.gpu.global.u32 [%0], %1;"
                         :: "l"(pp), "r"(target) : "memory");
        } else {
            unsigned cur;
            do {
                asm volatile("ld.acquire.gpu.global.u32 %0, [%1];"
                             : "=r"(cur) : "l"(pp) : "memory");
            } while (cur < target);
        }
    }
    __syncthreads();
}

// ---------------- kernel 0: prep ------------------------------------------------
__global__ void prep_kernel(const float* __restrict__ bi, const float* __restrict__ bh) {
    int i = blockIdx.x * blockDim.x + threadIdx.x;
    int stride = gridDim.x * blockDim.x;
    if (i < 128) { g_barc[i] = 0u; g_barp[i] = 0u; }
    if (i < FOURH) g_bsum[i] = bi[i] + bh[i];
    unsigned* gh = (unsigned*)g_h;                 // 2*64*512 bf16 = 32768 u32
    for (int j = i; j < 32768; j += stride) gh[j] = 0u;
}

// ---------------- kernel 1: xw = gather(emb, X) @ Wi + bsum  (bf16 HMMA) -------
// CTA tile 128m x 128n, BK=32, 8 warps 2(wm)x4(wn), warp tile 64x32,
// mma.m16n8k16 bf16; output stored bf16. Double-buffered smem.
// smem (u32): Asb[2][128][18] | Bsb[2][128][17]
#define XB_AS(buf, r, k) sm_u[(buf) * 2304 + (r) * 18 + (k)]
#define XB_BS(buf, c, k) sm_u[4608 + (buf) * 2176 + (c) * 17 + (k)]
#define SMEM_XW ((4608 + 4352) * 4)

__global__ __launch_bounds__(256, 2) void xw_bf16_kernel(
    const int* __restrict__ X, const float* __restrict__ emb,
    const float* __restrict__ Wi) {
    extern __shared__ __align__(16) unsigned sm_u[];
    __shared__ int tok[128];

    const int tid = threadIdx.x;
    const int m0 = blockIdx.y * 128;
    const int n0 = blockIdx.x * 128;
    const int lane = tid & 31, wrp = tid >> 5;
    const int wm = wrp >> 2, wn = wrp & 3;
    const int g = lane >> 2, tig = lane & 3;

    const int bkp = tid >> 5, bc4 = tid & 31;     // B loader: kpair base, col-quad

    if (tid < 128) {
        int m = m0 + tid;
        tok[tid] = X[(m & 63) * STEPS + (m >> 6)];
    }
    __syncthreads();

    float acc[4][4][4];
#pragma unroll
    for (int mt = 0; mt < 4; ++mt)
#pragma unroll
        for (int nt = 0; nt < 4; ++nt)
#pragma unroll
            for (int j = 0; j < 4; ++j) acc[mt][nt][j] = 0.0f;

    // prefetch k-tile 0
    float4 pa[4];           // A: 4 chunks (row = id>>3, kc = id&7)
    float4 pw[2][2];        // B: q in {0,1}: two k-rows (2*kp, 2*kp+1)
#pragma unroll
    for (int q = 0; q < 4; ++q) {
        int id = tid + q * 256;
        pa[q] = *(const float4*)(emb + (size_t)tok[id >> 3] * EMB + (id & 7) * 4);
    }
#pragma unroll
    for (int q = 0; q < 2; ++q) {
        int k0 = (bkp + q * 8) * 2;
        pw[q][0] = *(const float4*)(Wi + (size_t)k0 * FOURH + n0 + bc4 * 4);
        pw[q][1] = *(const float4*)(Wi + (size_t)(k0 + 1) * FOURH + n0 + bc4 * 4);
    }

    int cur = 0;
    for (int kt = 0; kt < EMB; kt += 32) {
        // store A (bf16x2 pairs along k)
#pragma unroll
        for (int q = 0; q < 4; ++q) {
            int id = tid + q * 256;
            int row = id >> 3, kc = id & 7;
            XB_AS(cur, row, kc * 2)     = pack_bf16(pa[q].x, pa[q].y);
            XB_AS(cur, row, kc * 2 + 1) = pack_bf16(pa[q].z, pa[q].w);
        }
        // store B: Bsb[c][kp] = bf16x2(Wi[2kp][c], Wi[2kp+1][c])
#pragma unroll
        for (int q = 0; q < 2; ++q) {
            int kp = bkp + q * 8;
            const float* w0 = (const float*)&pw[q][0];
            const float* w1 = (const float*)&pw[q][1];
#pragma unroll
            for (int j = 0; j < 4; ++j)
                XB_BS(cur, bc4 * 4 + j, kp) = pack_bf16(w0[j], w1[j]);
        }
        if (kt + 32 < EMB) {
            int kn = kt + 32;
#pragma unroll
            for (int q = 0; q < 4; ++q) {
                int id = tid + q * 256;
                pa[q] = *(const float4*)(emb + (size_t)tok[id >> 3] * EMB + kn + (id & 7) * 4);
            }
#pragma unroll
            for (int q = 0; q < 2; ++q) {
                int k0 = kn + (bkp + q * 8) * 2;
                pw[q][0] = *(const float4*)(Wi + (size_t)k0 * FOURH + n0 + bc4 * 4);
                pw[q][1] = *(const float4*)(Wi + (size_t)(k0 + 1) * FOURH + n0 + bc4 * 4);
            }
        }
        __syncthreads();

#pragma unroll
        for (int s = 0; s < 2; ++s) {            // two k16 sub-tiles
            unsigned a[4][4], b[4][2];
#pragma unroll
            for (int mt = 0; mt < 4; ++mt) {
                int r = wm * 64 + mt * 16 + g;
                a[mt][0] = XB_AS(cur, r,     s * 8 + tig);
                a[mt][1] = XB_AS(cur, r + 8, s * 8 + tig);
                a[mt][2] = XB_AS(cur, r,     s * 8 + tig + 4);
                a[mt][3] = XB_AS(cur, r + 8, s * 8 + tig + 4);
            }
#pragma unroll
            for (int nt = 0; nt < 4; ++nt) {
                int c = wn * 32 + nt * 8 + g;
                b[nt][0] = XB_BS(cur, c, s * 8 + tig);
                b[nt][1] = XB_BS(cur, c, s * 8 + tig + 4);
            }
#pragma unroll
            for (int mt = 0; mt < 4; ++mt)
#pragma unroll
                for (int nt = 0; nt < 4; ++nt)
                    mma_bf16(acc[mt][nt], a[mt], b[nt]);
        }
        cur ^= 1;
        __syncthreads();
    }

    // epilogue: + bsum, pack to bf16x2, one u32 store per pair
    float bs0[4], bs1[4];
#pragma unroll
    for (int nt = 0; nt < 4; ++nt) {
        int c = n0 + wn * 32 + nt * 8 + tig * 2;
        bs0[nt] = g_bsum[c];
        bs1[nt] = g_bsum[c + 1];
    }
#pragma unroll
    for (int mt = 0; mt < 4; ++mt) {
        int r = m0 + wm * 64 + mt * 16 + g;
#pragma unroll
        for (int nt = 0; nt < 4; ++nt) {
            int c = n0 + wn * 32 + nt * 8 + tig * 2;
            *(unsigned*)(g_xw + (size_t)r * FOURH + c) =
                pack_bf16(acc[mt][nt][0] + bs0[nt], acc[mt][nt][1] + bs1[nt]);
            *(unsigned*)(g_xw + (size_t)(r + 8) * FOURH + c) =
                pack_bf16(acc[mt][nt][2] + bs0[nt], acc[mt][nt][3] + bs1[nt]);
        }
    }
}

// ---------------- kernel 2: persistent LSTM (R12/R15 body; bf16 xw reads) -----
// 128 CTAs = 32 col-groups (16 hidden units = 64 gate cols) x 4 batch-groups(16).
// smem (u32): h_s[16][260] | wf[32 i16][8 nt][32 ln][2] | spre2 f32[2][64][17]
#define LSTM_SMEM ((4160 + 16384 + 2176) * 4)

__global__ __launch_bounds__(256, 1) void lstm_bf16_kernel(const float* __restrict__ Wh) {
    extern __shared__ __align__(16) unsigned smu[];
    unsigned* h_s   = smu;                          // [16][260] u32 (bf16x2)
    unsigned* wf    = smu + 4160;                   // [32][8][32][2]
    float*    spre2 = (float*)(smu + 4160 + 16384); // [2][64][17]

    const int tid  = threadIdx.x;
    const int cta  = blockIdx.x;
    const int colg = cta >> 2;          // 0..31 (16 hidden units each)
    const int bg   = cta & 3;           // batch quarter (barrier domain)
    const int lane = tid & 31, wid = tid >> 5;
    const int g = lane >> 2, tig = lane & 3;
    const int ntp = wid & 3, kh = wid >> 2;

    const unsigned hs_addr = (unsigned)__cvta_generic_to_shared(h_s);

    // one-time: pack this CTA's 64 Wh columns into bf16 B-fragment layout
    for (int idx = tid; idx < 16384; idx += 256) {
        int reg = idx & 1;
        int ln  = (idx >> 1) & 31;
        int nt8 = (idx >> 6) & 7;               // n-tile 0..7
        int i16 = idx >> 9;                     // k16 tile 0..31
        int lg = ln >> 2, ltig = ln & 3;
        int k0 = i16 * 16 + 2 * ltig + reg * 8;
        int c  = nt8 * 8 + lg;                  // local col 0..63
        int gc = (c >> 4) * HID + colg * 16 + (c & 15);
        wf[idx] = pack_bf16(Wh[(size_t)k0 * FOURH + gc],
                            Wh[(size_t)(k0 + 1) * FOURH + gc]);
    }

    const int ub = tid >> 4, uu = tid & 15;     // update: local batch, unit
    float creg = 0.0f;

    const unsigned* ha = h_s + g * 260 + tig;
    const unsigned* hb = ha + 8 * 260;

    __syncthreads();

    for (int t = 0; t < STEPS; ++t) {
        const __nv_bfloat16* hin = g_h + (t & 1) * BATCH * HID;
        __nv_bfloat16*      hout = g_h + ((t + 1) & 1) * BATCH * HID;
        const __nv_bfloat16* xwt = g_xw + (size_t)t * BATCH * FOURH
                                   + (size_t)(bg * 16 + ub) * FOURH + colg * 16 + uu;

        // prefetch this step's xw gate biases (bf16 -> fp32)
        float x0 = ldcs_bf16(xwt);
        float x1 = ldcs_bf16(xwt + 512);
        float x2 = ldcs_bf16(xwt + 1024);
        float x3 = ldcs_bf16(xwt + 1536);

        // stage 16 bf16 h rows (16 KB), row stride 1040 B
#pragma unroll
        for (int j = 0; j < 4; ++j) {
            int i = tid + j * 256;              // 16B chunk 0..1023
            int row = i >> 6, cc = i & 63;
            cpasync16(hs_addr + (unsigned)(row * 1040 + cc * 16),
                      (const char*)hin + (size_t)(bg * 16 + row) * 1024 + cc * 16);
        }
        asm volatile("cp.async.commit_group;");
        asm volatile("cp.async.wait_group 0;" ::: "memory");
        __syncthreads();

        // bf16 mma over this warp's k-half (16 k16-tiles, 2 n-tiles)
        float acc0[4] = {0.f, 0.f, 0.f, 0.f};
        float acc1[4] = {0.f, 0.f, 0.f, 0.f};
#pragma unroll 8
        for (int i16 = kh * 16; i16 < kh * 16 + 16; ++i16) {
            unsigned a[4];
            a[0] = ha[i16 * 8];
            a[1] = hb[i16 * 8];
            a[2] = ha[i16 * 8 + 4];
            a[3] = hb[i16 * 8 + 4];
            const unsigned* wb = wf + ((i16 * 8 + ntp * 2) * 32 + lane) * 2;
            uint2 b0 = *(const uint2*)wb;
            uint2 b1 = *(const uint2*)(wb + 64);
            mma_bf16(acc0, a, (const unsigned*)&b0);
            mma_bf16(acc1, a, (const unsigned*)&b1);
        }

        // write per-k-half partials: spre2[kh][col 0..63][batch 0..15]
        {
            float* sp = spre2 + kh * 1088;
            int c0 = ntp * 16 + tig * 2;
            sp[(c0)     * 17 + g]     = acc0[0];
            sp[(c0 + 1) * 17 + g]     = acc0[1];
            sp[(c0)     * 17 + g + 8] = acc0[2];
            sp[(c0 + 1) * 17 + g + 8] = acc0[3];
            sp[(c0 + 8) * 17 + g]     = acc1[0];
            sp[(c0 + 9) * 17 + g]     = acc1[1];
            sp[(c0 + 8) * 17 + g + 8] = acc1[2];
            sp[(c0 + 9) * 17 + g + 8] = acc1[3];
        }
        __syncthreads();

        // cell update: thread -> (local batch ub 0..15, unit uu 0..15)
        {
            float pi = spre2[(0  + uu) * 17 + ub] + spre2[1088 + (0  + uu) * 17 + ub] + x0;
            float pf = spre2[(16 + uu) * 17 + ub] + spre2[1088 + (16 + uu) * 17 + ub] + x1;
            float pg = spre2[(32 + uu) * 17 + ub] + spre2[1088 + (32 + uu) * 17 + ub] + x2;
            float po = spre2[(48 + uu) * 17 + ub] + spre2[1088 + (48 + uu) * 17 + ub] + x3;
            float ig = fsigmoid_(pi);
            float fg = fsigmoid_(pf);
            float gg = ftanh_(pg);
            float og = fsigmoid_(po);
            creg = fg * creg + ig * gg;
            float hh = og * ftanh_(creg);
            size_t hidx = (size_t)(bg * 16 + ub) * HID + colg * 16 + uu;
            hout[hidx] = __float2bfloat16(hh);
            if (t == STEPS - 1) g_hf[hidx] = hh;   // fp32 copy for outproj
        }
        domain_barrier(bg, (unsigned)(t + 1));
    }
}

// ---------------- kernel 3: out^T tile via tf32 mma (R14, known-good) ---------
#define OP_AS(buf, k, b) smo[(buf) * 1088 + (k) * 68 + (b)]
#define OP_BS(buf, k, c) smo[2176 + (buf) * 4224 + (k) * 264 + (c)]
#define SMEM_OP ((2176 + 8448) * 4)

__global__ __launch_bounds__(256, 2) void outproj_tf32_kernel(
    const float* __restrict__ Wout, const float* __restrict__ bout,
    float* __restrict__ out) {
    extern __shared__ __align__(16) unsigned smo[];

    const int tid = threadIdx.x;
    const int n0 = blockIdx.x * 256;
    const int lane = tid & 31, wrp = tid >> 5;   // wrp = n-group 0..7
    const int g = lane >> 2, tig = lane & 3;
    const float* h = g_hf;

    const int brow = tid >> 2, bc4 = tid & 3;    // B loader: row 0..63 (+64q)

    float acc[4][4][4];
#pragma unroll
    for (int mt = 0; mt < 4; ++mt)
#pragma unroll
        for (int nt = 0; nt < 4; ++nt)
#pragma unroll
            for (int j = 0; j < 4; ++j) acc[mt][nt][j] = 0.0f;

    float  ph[4];
    float4 pw[4];
#pragma unroll
    for (int q = 0; q < 4; ++q) {
        int id = tid + q * 256;
        ph[q] = h[(id >> 4) * HID + (id & 15)];
        int row = n0 + brow + q * 64;
        pw[q] = (row < NCLASS) ? *(const float4*)(Wout + (size_t)row * HID + bc4 * 4)
                               : make_float4(0.f, 0.f, 0.f, 0.f);
    }

    int cur = 0;
    for (int kt = 0; kt < HID; kt += 16) {
#pragma unroll
        for (int q = 0; q < 4; ++q) {
            int id = tid + q * 256;
            OP_AS(cur, id & 15, id >> 4) = cvt_tf32(ph[q]);
            uint4 w = cvt_tf32x4(pw[q]);
            OP_BS(cur, bc4 * 4 + 0, brow + q * 64) = w.x;
            OP_BS(cur, bc4 * 4 + 1, brow + q * 64) = w.y;
            OP_BS(cur, bc4 * 4 + 2, brow + q * 64) = w.z;
            OP_BS(cur, bc4 * 4 + 3, brow + q * 64) = w.w;
        }
        if (kt + 16 < HID) {
            int kn = kt + 16;
#pragma unroll
            for (int q = 0; q < 4; ++q) {
                int id = tid + q * 256;
                ph[q] = h[(id >> 4) * HID + kn + (id & 15)];
                int row = n0 + brow + q * 64;
                pw[q] = (row < NCLASS) ? *(const float4*)(Wout + (size_t)row * HID + kn + bc4 * 4)
                                       : make_float4(0.f, 0.f, 0.f, 0.f);
            }
        }
        __syncthreads();

#pragma unroll
        for (int k8 = 0; k8 < 2; ++k8) {
            const int k0 = k8 * 8;
            unsigned a[4][4], b[4][2];
#pragma unroll
            for (int mt = 0; mt < 4; ++mt) {
                int r = mt * 16 + g;
                a[mt][0] = OP_AS(cur, k0 + tig,     r);
                a[mt][1] = OP_AS(cur, k0 + tig,     r + 8);
                a[mt][2] = OP_AS(cur, k0 + tig + 4, r);
                a[mt][3] = OP_AS(cur, k0 + tig + 4, r + 8);
            }
#pragma unroll
            for (int nt = 0; nt < 4; ++nt) {
                int c = wrp * 32 + nt * 8 + g;
                b[nt][0] = OP_BS(cur, k0 + tig,     c);
                b[nt][1] = OP_BS(cur, k0 + tig + 4, c);
            }
#pragma unroll
            for (int mt = 0; mt < 4; ++mt)
#pragma unroll
                for (int nt = 0; nt < 4; ++nt)
                    mma_tf32(acc[mt][nt], a[mt], b[nt]);
        }
        cur ^= 1;
    }

    // epilogue: scalar stores (NCLASS odd -> odd rows only 4B aligned)
#pragma unroll
    for (int nt = 0; nt < 4; ++nt) {
        int n = n0 + wrp * 32 + nt * 8 + tig * 2;
        if (n >= NCLASS) continue;
        float bo0 = bout[n];
        bool has1 = (n + 1 < NCLASS);
        float bo1 = has1 ? bout[n + 1] : 0.0f;
#pragma unroll
        for (int mt = 0; mt < 4; ++mt) {
            int b0r = mt * 16 + g;
            out[(size_t)b0r * NCLASS + n] = acc[mt][nt][0] + bo0;
            out[(size_t)(b0r + 8) * NCLASS + n] = acc[mt][nt][2] + bo0;
            if (has1) {
                out[(size_t)b0r * NCLASS + n + 1] = acc[mt][nt][1] + bo1;
                out[(size_t)(b0r + 8) * NCLASS + n + 1] = acc[mt][nt][3] + bo1;
            }
        }
    }
}

// ---------------- launch --------------------------------------------------------
extern "C" void kernel_launch(void* const* d_in, const int* in_sizes, int n_in,
                              void* d_out, int out_size) {
    const int*   X    = (const int*)d_in[0];
    const float* emb  = (const float*)d_in[1];
    const float* Wi   = (const float*)d_in[2];
    const float* Wh   = (const float*)d_in[3];
    const float* bi   = (const float*)d_in[4];
    const float* bh   = (const float*)d_in[5];
    // d_in[6..9]: layer-2 params — provably unused by the reference output
    const float* Wout = (const float*)d_in[10];
    const float* bout = (const float*)d_in[11];
    float* out = (float*)d_out;

    // allow >48KB dynamic smem (attribute only, not an allocation; idempotent)
    cudaFuncSetAttribute(lstm_bf16_kernel,
                         cudaFuncAttributeMaxDynamicSharedMemorySize, LSTM_SMEM);
    cudaFuncSetAttribute(xw_bf16_kernel,
                         cudaFuncAttributeMaxDynamicSharedMemorySize, SMEM_XW);
    cudaFuncSetAttribute(outproj_tf32_kernel,
                         cudaFuncAttributeMaxDynamicSharedMemorySize, SMEM_OP);

    prep_kernel<<<64, 256>>>(bi, bh);
    xw_bf16_kernel<<<dim3(FOURH / 128, (STEPS * BATCH) / 128), 256, SMEM_XW>>>(X, emb, Wi);
    lstm_bf16_kernel<<<128, 256, LSTM_SMEM>>>(Wh);
    outproj_tf32_kernel<<<(NCLASS + 255) / 256, 256, SMEM_OP>>>(Wout, bout, out);
}